// round 16
// baseline (speedup 1.0000x reference)
#include <cuda_runtime.h>
#include <cstdint>

// CSCFCLayer: out[b][n] = sum_{f<64} x[b][(n+f)%C] * kernel[(n+f)%C][n] + bias[n]
// B=128, C=N=8192, F=64, fp32.
//
// v16: A lives in REGISTERS (40 LDG/thread at kernel start, fully unrolled use),
// B via pure cp.async (zfill for out-of-band slots -> no pre-zero, no extra
// barrier). One __syncthreads total. Band-trimmed m16n8k8 tf32 (both operands
// tf32-truncated raw fp32). Grid 128, 1024 threads.
//  - smem: only Bs [128 k][72] (~37KB).
//  - Mainloop step: 4 LDS.32 (B) + 2 MMA; A operands already in regs.
//  - Epilogue: direct STG.64 + bias (loaded late to save regs).

#define CDIM 8192
#define NDIM 8192
#define NT 64
#define THREADS 1024
#define BSTRIDE 72
#define SMEM_NEED (128 * BSTRIDE * 4)

__device__ __forceinline__ void mma_tf32(float* c,
                                         uint32_t a0, uint32_t a1,
                                         uint32_t a2, uint32_t a3,
                                         uint32_t b0, uint32_t b1) {
    asm volatile(
        "mma.sync.aligned.m16n8k8.row.col.f32.tf32.tf32.f32 "
        "{%0,%1,%2,%3}, {%4,%5,%6,%7}, {%8,%9}, {%0,%1,%2,%3};"
        : "+f"(c[0]), "+f"(c[1]), "+f"(c[2]), "+f"(c[3])
        : "r"(a0), "r"(a1), "r"(a2), "r"(a3), "r"(b0), "r"(b1));
}

extern "C" __global__ void __launch_bounds__(THREADS, 1)
cscfc_mma_kernel(const float* __restrict__ x,
                 const float* __restrict__ w,
                 const float* __restrict__ bias,
                 float* __restrict__ out)
{
    extern __shared__ float Bs[];   // [128 k][BSTRIDE] raw fp32 banded weights [k][n]

    const int tid  = threadIdx.x;
    const int lane = tid & 31;
    const int wid  = tid >> 5;
    const int n0   = blockIdx.x * NT;

    const int mw = wid & 7;         // row group (16 rows)
    const int nw = wid >> 3;        // col group (16 cols)
    const int g  = lane >> 2;       // 0..7
    const int tg = lane & 3;        // 0..3

    const unsigned bs_u = (unsigned)__cvta_generic_to_shared(Bs);

    // ---- B fill, pure cp.async: row cl valid cols [lo, hi] contiguous.
    //      8 threads/row; thread j handles 16B slots j, j+8. In-band slots:
    //      16B cp.async with src-size zero-fill tail; unaligned head: 4B copies;
    //      fully out-of-band slots: bytes=0 zfill (no src read). ----
    {
        const int cl = tid >> 3;     // 0..127
        const int j  = tid & 7;
        const int r  = (n0 + cl) & (CDIM - 1);
        const float* wr = w + (size_t)r * NDIM + n0;
        const int lo = (cl - 63 > 0) ? cl - 63 : 0;
        const int hi = (cl < 63) ? cl : 63;
        const unsigned brow = bs_u + (unsigned)(cl * BSTRIDE) * 4u;
#pragma unroll
        for (int t = 0; t < 2; ++t) {
            const int s  = j + t * 8;
            const int sl = s * 4;
            const int sr = sl + 3;
            if (sl > hi || sr < lo) {
                // outside band: pure zero-fill, no source read
                asm volatile("cp.async.ca.shared.global [%0], [%1], 16, 0;"
                             :: "r"(brow + (unsigned)sl * 4u), "l"(wr + sl) : "memory");
            } else if (sl >= lo) {
                const int he = (sr < hi) ? sr : hi;
                const unsigned bytes = (unsigned)(he - sl + 1) * 4u;  // 4..16
                asm volatile("cp.async.ca.shared.global [%0], [%1], 16, %2;"
                             :: "r"(brow + (unsigned)sl * 4u),
                                "l"(wr + sl), "r"(bytes) : "memory");
            } else {
                // unaligned head: zero low part, copy valid 4B elements
                asm volatile("cp.async.ca.shared.global [%0], [%1], 16, 0;"
                             :: "r"(brow + (unsigned)sl * 4u), "l"(wr + sl) : "memory");
                const int he = (sr < hi) ? sr : hi;
                for (int n = lo; n <= he; ++n)
                    asm volatile("cp.async.ca.shared.global [%0], [%1], 4;"
                                 :: "r"(brow + (unsigned)n * 4u),
                                    "l"(wr + n) : "memory");
            }
        }
        asm volatile("cp.async.commit_group;" ::: "memory");
    }

    // ---- A into registers: 2 rows x 20 cols per thread (stride-4), LDGs
    //      overlap the B async fill. Wrap only in the last tile. ----
    uint32_t ar[2][20];
    {
        const int row = mw * 16 + g;
        if (n0 + NT + 64 <= CDIM) {
            const float* xr = x + (size_t)row * CDIM + n0 + nw * 16 + tg;
#pragma unroll
            for (int t = 0; t < 20; ++t) {
                ar[0][t] = __float_as_uint(__ldg(xr + 4 * t));
                ar[1][t] = __float_as_uint(__ldg(xr + 8 * CDIM + 4 * t));
            }
        } else {
            const float* x0 = x + (size_t)row * CDIM;
#pragma unroll
            for (int t = 0; t < 20; ++t) {
                const int c = (n0 + nw * 16 + tg + 4 * t) & (CDIM - 1);
                ar[0][t] = __float_as_uint(__ldg(x0 + c));
                ar[1][t] = __float_as_uint(__ldg(x0 + 8 * CDIM + c));
            }
        }
    }

    asm volatile("cp.async.wait_group 0;" ::: "memory");
    __syncthreads();   // the only barrier (B visibility)

    // ---- Mainloop: warp (mw, nw): rows mw*16..+15, cols nw*16..+15,
    //      k = 16nw .. 16nw+79 (band-trimmed, 10 unrolled k8-steps). ----
    float acc[2][4] = {{0.f, 0.f, 0.f, 0.f}, {0.f, 0.f, 0.f, 0.f}};

    const uint32_t* Bq = (const uint32_t*)Bs + (nw * 16 + tg) * BSTRIDE + nw * 16 + g;

#pragma unroll
    for (int s = 0; s < 10; ++s) {
        const int k0 = s * 8;
        const uint32_t b0 = Bq[k0 * BSTRIDE];
        const uint32_t b1 = Bq[(k0 + 4) * BSTRIDE];
        const uint32_t b2 = Bq[k0 * BSTRIDE + 8];
        const uint32_t b3 = Bq[(k0 + 4) * BSTRIDE + 8];
        mma_tf32(acc[0], ar[0][2 * s], ar[1][2 * s], ar[0][2 * s + 1], ar[1][2 * s + 1], b0, b1);
        mma_tf32(acc[1], ar[0][2 * s], ar[1][2 * s], ar[0][2 * s + 1], ar[1][2 * s + 1], b2, b3);
    }

    // ---- Epilogue: bias (loaded late) + direct STG.64. ----
    {
        const float2 bz0 = *(const float2*)(bias + n0 + nw * 16 + tg * 2);
        const float2 bz1 = *(const float2*)(bias + n0 + nw * 16 + 8 + tg * 2);
        const int row = mw * 16 + g;
        const int c0  = n0 + nw * 16 + tg * 2;
        float* o0 = out + (size_t)row * NDIM + c0;
        float* o1 = out + (size_t)(row + 8) * NDIM + c0;
        *(float2*)o0       = make_float2(acc[0][0] + bz0.x, acc[0][1] + bz0.y);
        *(float2*)o1       = make_float2(acc[0][2] + bz0.x, acc[0][3] + bz0.y);
        *(float2*)(o0 + 8) = make_float2(acc[1][0] + bz1.x, acc[1][1] + bz1.y);
        *(float2*)(o1 + 8) = make_float2(acc[1][2] + bz1.x, acc[1][3] + bz1.y);
    }
}

extern "C" void kernel_launch(void* const* d_in, const int* in_sizes, int n_in,
                              void* d_out, int out_size) {
    const float* x    = (const float*)d_in[0];
    const float* w    = (const float*)d_in[1];
    const float* bias = (const float*)d_in[2];
    float* out        = (float*)d_out;

    cudaFuncSetAttribute(cscfc_mma_kernel,
                         cudaFuncAttributeMaxDynamicSharedMemorySize, SMEM_NEED);
    cscfc_mma_kernel<<<NDIM / NT, THREADS, SMEM_NEED>>>(x, w, bias, out);
}

// round 17
// speedup vs baseline: 1.4536x; 1.4536x over previous
#include <cuda_runtime.h>
#include <cstdint>

// CSCFCLayer: out[b][n] = sum_{f<64} x[b][(n+f)%C] * kernel[(n+f)%C][n] + bias[n]
// B=128, C=N=8192, F=64, fp32.
//
// v17 = v15 (async-fill band-trimmed m16n8k8 tf32, grid 128, 1024 thr) minus the
// Bs pre-zero pass and its barrier:
//  - out-of-band B slots zeroed via cp.async zfill (cp-size 16, src-size 0);
//  - in-band tails zero-filled via src-size < 16;
//  - unaligned heads: sub-band words zeroed by non-overlapping STS.32, valid
//    words copied by 4B cp.async (no overlapping async writes).
// One commit group, one wait, ONE __syncthreads. Direct-STG epilogue.

#define CDIM 8192
#define NDIM 8192
#define NT 64
#define THREADS 1024
#define ASTRIDE 132
#define BSTRIDE 72
#define A_FLOATS (128 * ASTRIDE)
#define SMEM_NEED ((A_FLOATS + 128 * BSTRIDE) * 4)

__device__ __forceinline__ void mma_tf32(float* c,
                                         uint32_t a0, uint32_t a1,
                                         uint32_t a2, uint32_t a3,
                                         uint32_t b0, uint32_t b1) {
    asm volatile(
        "mma.sync.aligned.m16n8k8.row.col.f32.tf32.tf32.f32 "
        "{%0,%1,%2,%3}, {%4,%5,%6,%7}, {%8,%9}, {%0,%1,%2,%3};"
        : "+f"(c[0]), "+f"(c[1]), "+f"(c[2]), "+f"(c[3])
        : "r"(a0), "r"(a1), "r"(a2), "r"(a3), "r"(b0), "r"(b1));
}

extern "C" __global__ void __launch_bounds__(THREADS, 1)
cscfc_mma_kernel(const float* __restrict__ x,
                 const float* __restrict__ w,
                 const float* __restrict__ bias,
                 float* __restrict__ out)
{
    extern __shared__ float sm[];
    float* As = sm;               // [128 b][ASTRIDE] raw fp32 x window
    float* Bs = sm + A_FLOATS;    // [128 k][BSTRIDE] raw fp32 banded weights [k][n]

    const int tid  = threadIdx.x;
    const int lane = tid & 31;
    const int wid  = tid >> 5;
    const int n0   = blockIdx.x * NT;

    const int mw = wid & 7;       // row group (16 rows)
    const int nw = wid >> 3;      // col group (16 cols)
    const int g  = lane >> 2;     // 0..7
    const int tg = lane & 3;      // 0..3

    const unsigned as_u = (unsigned)__cvta_generic_to_shared(As);
    const unsigned bs_u = (unsigned)__cvta_generic_to_shared(Bs);

    // ---- A fill: raw x window via 16B cp.async (4/thread). ----
    {
        const int b = tid >> 3;
        const int q = tid & 7;
#pragma unroll
        for (int kc = 0; kc < 4; ++kc) {
            const int col = kc * 32 + q * 4;
            const int c = (n0 + col) & (CDIM - 1);
            asm volatile("cp.async.cg.shared.global [%0], [%1], 16;"
                         :: "r"(as_u + (unsigned)(b * ASTRIDE + col) * 4u),
                            "l"(x + (size_t)b * CDIM + c) : "memory");
        }
    }

    // ---- B fill, single pass: row cl valid cols [lo, hi] contiguous.
    //      8 threads/row; thread j owns 16B slots j and j+8. ----
    {
        const int cl = tid >> 3;           // 0..127
        const int j  = tid & 7;
        const int r  = (n0 + cl) & (CDIM - 1);
        const float* wr = w + (size_t)r * NDIM + n0;
        const int lo = (cl - 63 > 0) ? cl - 63 : 0;
        const int hi = (cl < 63) ? cl : 63;
        const unsigned brow = bs_u + (unsigned)(cl * BSTRIDE) * 4u;
#pragma unroll
        for (int t = 0; t < 2; ++t) {
            const int s  = j + t * 8;
            const int sl = s * 4;
            const int sr = sl + 3;
            if (sl > hi || sr < lo) {
                // fully outside band: pure zero-fill (src not read)
                asm volatile("cp.async.ca.shared.global [%0], [%1], 16, 0;"
                             :: "r"(brow + (unsigned)sl * 4u), "l"(wr) : "memory");
            } else if (sl >= lo) {
                // aligned start; zero-fill tail beyond hi via src-size
                const int he = (sr < hi) ? sr : hi;
                const unsigned bytes = (unsigned)(he - sl + 1) * 4u;   // 4..16
                asm volatile("cp.async.ca.shared.global [%0], [%1], 16, %2;"
                             :: "r"(brow + (unsigned)sl * 4u),
                                "l"(wr + sl), "r"(bytes) : "memory");
            } else {
                // unaligned head: STS zeros below lo (non-overlapping), then 4B copies
                for (int n = sl; n < lo; ++n)
                    Bs[cl * BSTRIDE + n] = 0.0f;
                const int he = (sr < hi) ? sr : hi;
                for (int n = lo; n <= he; ++n)
                    asm volatile("cp.async.ca.shared.global [%0], [%1], 4;"
                                 :: "r"(brow + (unsigned)n * 4u),
                                    "l"(wr + n) : "memory");
            }
        }
    }
    asm volatile("cp.async.commit_group;" ::: "memory");

    // ---- bias prefetch. ----
    const float2 bz0 = *(const float2*)(bias + n0 + nw * 16 + tg * 2);
    const float2 bz1 = *(const float2*)(bias + n0 + nw * 16 + 8 + tg * 2);

    asm volatile("cp.async.wait_group 0;" ::: "memory");
    __syncthreads();   // the only barrier

    // ---- Mainloop: warp (mw, nw): rows mw*16..+15, cols nw*16..+15,
    //      k = 16nw .. 16nw+79 (band-trimmed, 10 unrolled k8-steps).
    //      A and B raw fp32 bits -> tf32 truncation in HMMA. ----
    float acc[2][4] = {{0.f, 0.f, 0.f, 0.f}, {0.f, 0.f, 0.f, 0.f}};

    const float*    Ap = As + (mw * 16 + g) * ASTRIDE + tg + nw * 16;
    const uint32_t* Bq = (const uint32_t*)Bs + (nw * 16 + tg) * BSTRIDE + nw * 16 + g;

#pragma unroll
    for (int s = 0; s < 10; ++s) {
        const int k0 = s * 8;
        const uint32_t a0 = __float_as_uint(Ap[k0]);
        const uint32_t a1 = __float_as_uint(Ap[8 * ASTRIDE + k0]);
        const uint32_t a2 = __float_as_uint(Ap[k0 + 4]);
        const uint32_t a3 = __float_as_uint(Ap[8 * ASTRIDE + k0 + 4]);
        const uint32_t b0 = Bq[k0 * BSTRIDE];
        const uint32_t b1 = Bq[(k0 + 4) * BSTRIDE];
        const uint32_t b2 = Bq[k0 * BSTRIDE + 8];
        const uint32_t b3 = Bq[(k0 + 4) * BSTRIDE + 8];
        mma_tf32(acc[0], a0, a1, a2, a3, b0, b1);
        mma_tf32(acc[1], a0, a1, a2, a3, b2, b3);
    }

    // ---- Epilogue: direct STG.64 + bias. ----
    {
        const int row = mw * 16 + g;
        const int c0  = n0 + nw * 16 + tg * 2;
        float* o0 = out + (size_t)row * NDIM + c0;
        float* o1 = out + (size_t)(row + 8) * NDIM + c0;
        *(float2*)o0       = make_float2(acc[0][0] + bz0.x, acc[0][1] + bz0.y);
        *(float2*)o1       = make_float2(acc[0][2] + bz0.x, acc[0][3] + bz0.y);
        *(float2*)(o0 + 8) = make_float2(acc[1][0] + bz1.x, acc[1][1] + bz1.y);
        *(float2*)(o1 + 8) = make_float2(acc[1][2] + bz1.x, acc[1][3] + bz1.y);
    }
}

extern "C" void kernel_launch(void* const* d_in, const int* in_sizes, int n_in,
                              void* d_out, int out_size) {
    const float* x    = (const float*)d_in[0];
    const float* w    = (const float*)d_in[1];
    const float* bias = (const float*)d_in[2];
    float* out        = (float*)d_out;

    cudaFuncSetAttribute(cscfc_mma_kernel,
                         cudaFuncAttributeMaxDynamicSharedMemorySize, SMEM_NEED);
    cscfc_mma_kernel<<<NDIM / NT, THREADS, SMEM_NEED>>>(x, w, bias, out);
}